// round 10
// baseline (speedup 1.0000x reference)
#include <cuda_runtime.h>

#define EPSF 1e-5f
#define NN 10000
#define EE 160000
#define C1 256
#define C2 512
#define CAP 96   // max neighbors per node; in-degree ~ Poisson(16), max over 10k nodes ~ 45

// ---------------- scratch (static __device__ globals; addresses never taken on host) ----
__device__ float g_dis[NN];
__device__ int   g_cursor[NN];
__device__ int   g_csr[(size_t)NN * CAP];
__device__ __align__(16) float g_agg1[(size_t)NN * C1];
__device__ __align__(16) float g_t1[(size_t)NN * C2];
__device__ __align__(16) float g_y[(size_t)NN * C1];
__device__ __align__(16) float g_sumA[C2], g_sqA[C2], g_scaleA[C2], g_shiftA[C2];
__device__ __align__(16) float g_sumB[C1], g_sqB[C1], g_scaleB[C1], g_shiftB[C1];

// ---------------- graph preprocessing ----------------
__global__ void init_kernel(int n) {
    int i = blockIdx.x * blockDim.x + threadIdx.x;
    if (i < n) g_cursor[i] = 0;
    if (i < C2) { g_sumA[i] = 0.f; g_sqA[i] = 0.f; }
    if (i < C1) { g_sumB[i] = 0.f; g_sqB[i] = 0.f; }
}

// direct bucket scatter, 2 edges per thread
__global__ void fill_kernel(const int* __restrict__ es, int E, int n) {
    int e2 = (blockIdx.x * blockDim.x + threadIdx.x) * 2;
    if (e2 + 1 < E) {
        int2 rr = *(const int2*)&es[e2];
        int2 cc = *(const int2*)&es[E + e2];
        if ((unsigned)rr.x < (unsigned)n && (unsigned)cc.x < (unsigned)n) {
            int pos = atomicAdd(&g_cursor[cc.x], 1);
            if (pos < CAP) g_csr[(size_t)cc.x * CAP + pos] = rr.x;
        }
        if ((unsigned)rr.y < (unsigned)n && (unsigned)cc.y < (unsigned)n) {
            int pos = atomicAdd(&g_cursor[cc.y], 1);
            if (pos < CAP) g_csr[(size_t)cc.y * CAP + pos] = rr.y;
        }
    }
}

__global__ void dis_kernel(int n) {
    int i = blockIdx.x * blockDim.x + threadIdx.x;
    if (i < n) g_dis[i] = rsqrtf((float)(g_cursor[i] + 1));   // +1 self loop
}

// ---------------- normalized aggregation: out = D^-1/2 (A+I) D^-1/2 * in ----------------
// C = 256 -> 64 float4 lanes/node, 4 nodes per 256-thread block, grid-stride over nodes.
// Neighbor loop unrolled x4 with independent accumulators for MLP.
// phase 1 additionally accumulates BN-2 stats.
__global__ void __launch_bounds__(256) aggregate_kernel(const float4* __restrict__ xin,
                                                        float4* __restrict__ xout,
                                                        int phase, int nNodes) {
    const float4* in  = (phase == 0) ? xin : (const float4*)g_y;
    float4*       out = (phase == 0) ? (float4*)g_agg1 : xout;
    __shared__ float s_sum[4][C1];
    __shared__ float s_sq[4][C1];
    int sub = threadIdx.x >> 6;
    int l = threadIdx.x & 63;
    float4 ls = make_float4(0.f, 0.f, 0.f, 0.f);
    float4 lq = make_float4(0.f, 0.f, 0.f, 0.f);

    for (int node = blockIdx.x * 4 + sub; node < nNodes; node += gridDim.x * 4) {
        float dc = g_dis[node];
        float w0 = dc * dc;
        float4 v = __ldg(&in[(size_t)node * 64 + l]);
        float4 a0 = make_float4(v.x * w0, v.y * w0, v.z * w0, v.w * w0);
        float4 a1 = make_float4(0.f, 0.f, 0.f, 0.f);
        float4 a2 = make_float4(0.f, 0.f, 0.f, 0.f);
        float4 a3 = make_float4(0.f, 0.f, 0.f, 0.f);
        int base = node * CAP;
        int cnt = g_cursor[node];
        if (cnt > CAP) cnt = CAP;
        int i = 0;
        for (; i + 4 <= cnt; i += 4) {
            int4 rr = *(const int4*)&g_csr[base + i];
            float wA = __ldg(&g_dis[rr.x]) * dc;
            float wB = __ldg(&g_dis[rr.y]) * dc;
            float wC = __ldg(&g_dis[rr.z]) * dc;
            float wD = __ldg(&g_dis[rr.w]) * dc;
            float4 uA = __ldg(&in[(size_t)rr.x * 64 + l]);
            float4 uB = __ldg(&in[(size_t)rr.y * 64 + l]);
            float4 uC = __ldg(&in[(size_t)rr.z * 64 + l]);
            float4 uD = __ldg(&in[(size_t)rr.w * 64 + l]);
            a0.x += uA.x * wA; a0.y += uA.y * wA; a0.z += uA.z * wA; a0.w += uA.w * wA;
            a1.x += uB.x * wB; a1.y += uB.y * wB; a1.z += uB.z * wB; a1.w += uB.w * wB;
            a2.x += uC.x * wC; a2.y += uC.y * wC; a2.z += uC.z * wC; a2.w += uC.w * wC;
            a3.x += uD.x * wD; a3.y += uD.y * wD; a3.z += uD.z * wD; a3.w += uD.w * wD;
        }
        for (; i < cnt; i++) {
            int r = __ldg(&g_csr[base + i]);
            float w = __ldg(&g_dis[r]) * dc;
            float4 u = __ldg(&in[(size_t)r * 64 + l]);
            a1.x += u.x * w; a1.y += u.y * w; a1.z += u.z * w; a1.w += u.w * w;
        }
        float4 acc = make_float4(a0.x + a1.x + a2.x + a3.x,
                                 a0.y + a1.y + a2.y + a3.y,
                                 a0.z + a1.z + a2.z + a3.z,
                                 a0.w + a1.w + a2.w + a3.w);
        out[(size_t)node * 64 + l] = acc;
        if (phase == 1) {
            ls.x += acc.x; ls.y += acc.y; ls.z += acc.z; ls.w += acc.w;
            lq.x += acc.x * acc.x; lq.y += acc.y * acc.y;
            lq.z += acc.z * acc.z; lq.w += acc.w * acc.w;
        }
    }

    if (phase == 1) {
        int f = l << 2;
        s_sum[sub][f] = ls.x; s_sum[sub][f + 1] = ls.y;
        s_sum[sub][f + 2] = ls.z; s_sum[sub][f + 3] = ls.w;
        s_sq[sub][f] = lq.x; s_sq[sub][f + 1] = lq.y;
        s_sq[sub][f + 2] = lq.z; s_sq[sub][f + 3] = lq.w;
        __syncthreads();
        if (threadIdx.x < C1) {
            int t = threadIdx.x;
            float ts = s_sum[0][t] + s_sum[1][t] + s_sum[2][t] + s_sum[3][t];
            float tq = s_sq[0][t] + s_sq[1][t] + s_sq[2][t] + s_sq[3][t];
            atomicAdd(&g_sumB[t], ts);
            atomicAdd(&g_sqB[t], tq);
        }
    }
}

// ---------------- tf32 mma.sync GEMM with cp.async double buffering ----------------
// C[M,N] = A[M,K] * B[N,K]^T
// phase 0: A = g_agg1 [M,256], C = g_t1 [M,512]; epilogue accumulates BN-1 column stats
// phase 1: A = relu(g_t1*scaleA+shiftA) [M,512] (BN fused per-fragment), C = g_y [M,256]
// BM=BN=128, BK=32, 256 threads (8 warps, 4x2), warp tile 32x64, m16n8k8 tf32.
// smem holds raw fp32; tf32 convert happens at fragment load.

__device__ __forceinline__ unsigned f2tf(float f) {
    unsigned u;
    asm("cvt.rna.tf32.f32 %0, %1;" : "=r"(u) : "f"(f));
    return u;
}

__device__ __forceinline__ void mma_tf32(float* c, const unsigned* a, const unsigned* b) {
    asm volatile(
        "mma.sync.aligned.m16n8k8.row.col.f32.tf32.tf32.f32 "
        "{%0,%1,%2,%3}, {%4,%5,%6,%7}, {%8,%9}, {%0,%1,%2,%3};"
        : "+f"(c[0]), "+f"(c[1]), "+f"(c[2]), "+f"(c[3])
        : "r"(a[0]), "r"(a[1]), "r"(a[2]), "r"(a[3]), "r"(b[0]), "r"(b[1]));
}

__device__ __forceinline__ void cp16(void* smem_dst, const void* gmem_src, bool valid) {
    unsigned dst = (unsigned)__cvta_generic_to_shared(smem_dst);
    int sz = valid ? 16 : 0;
    asm volatile("cp.async.cg.shared.global [%0], [%1], 16, %2;"
                 :: "r"(dst), "l"(gmem_src), "r"(sz));
}

#define SMS 36                    // smem row stride (floats): bank = (4r + c) % 32, conflict-free
#define TILE_F (128 * SMS)        // floats per stage per matrix
#define GEMM_SMEM (4 * TILE_F * 4)  // 2 stages x 2 matrices, bytes = 73728

__global__ void __launch_bounds__(256) gemm_mma(const float* __restrict__ B,
                                                int M, int N, int K, int phase) {
    const float* A = (phase == 0) ? (const float*)g_agg1 : (const float*)g_t1;
    float*       C = (phase == 0) ? (float*)g_t1 : (float*)g_y;

    extern __shared__ float smem[];
    float* As = smem;                 // [2][128][SMS]
    float* Bs = smem + 2 * TILE_F;    // [2][128][SMS]
    __shared__ float s_sum[128];
    __shared__ float s_sq[128];

    int tid = threadIdx.x;
    int lane = tid & 31, wid = tid >> 5;
    int wm = (wid & 3) << 5;     // 0,32,64,96
    int wn = (wid >> 2) << 6;    // 0,64
    int m0 = blockIdx.y << 7, n0 = blockIdx.x << 7;

    float acc[2][8][4];
    #pragma unroll
    for (int mi = 0; mi < 2; mi++)
        #pragma unroll
        for (int ni = 0; ni < 8; ni++)
            #pragma unroll
            for (int j = 0; j < 4; j++) acc[mi][ni][j] = 0.f;

    int r = lane >> 2, cl = lane & 3;
    int ldr = tid >> 3;            // 0..31: row group base for loads
    int ldc = (tid & 7) << 2;      // 0,4,...,28

    int kTiles = K >> 5;

    // prologue: stage 0 <- tile 0
    {
        #pragma unroll
        for (int i = 0; i < 4; i++) {
            int row = ldr + (i << 5);
            cp16(&As[row * SMS + ldc], &A[(size_t)(m0 + row) * K + ldc], m0 + row < M);
            cp16(&Bs[row * SMS + ldc], &B[(size_t)(n0 + row) * K + ldc], true);
        }
        asm volatile("cp.async.commit_group;");
    }

    for (int t = 0; t < kTiles; t++) {
        int s = t & 1;
        if (t + 1 < kTiles) {
            int sn = (t + 1) & 1;
            int kofs = (t + 1) << 5;
            #pragma unroll
            for (int i = 0; i < 4; i++) {
                int row = ldr + (i << 5);
                cp16(&As[sn * TILE_F + row * SMS + ldc],
                     &A[(size_t)(m0 + row) * K + kofs + ldc], m0 + row < M);
                cp16(&Bs[sn * TILE_F + row * SMS + ldc],
                     &B[(size_t)(n0 + row) * K + kofs + ldc], true);
            }
            asm volatile("cp.async.commit_group;");
            asm volatile("cp.async.wait_group 1;");
        } else {
            asm volatile("cp.async.wait_group 0;");
        }
        __syncthreads();

        // preload BN params for this k-tile (phase 1)
        float scv[4][2], shv[4][2];
        if (phase == 1) {
            int kb = t << 5;
            #pragma unroll
            for (int kkj = 0; kkj < 4; kkj++) {
                scv[kkj][0] = __ldg(&g_scaleA[kb + (kkj << 3) + cl]);
                scv[kkj][1] = __ldg(&g_scaleA[kb + (kkj << 3) + cl + 4]);
                shv[kkj][0] = __ldg(&g_shiftA[kb + (kkj << 3) + cl]);
                shv[kkj][1] = __ldg(&g_shiftA[kb + (kkj << 3) + cl + 4]);
            }
        }

        const float* Asb = As + s * TILE_F;
        const float* Bsb = Bs + s * TILE_F;

        #pragma unroll
        for (int kkj = 0; kkj < 4; kkj++) {
            int kk = kkj << 3;
            unsigned a[2][4], b[8][2];
            #pragma unroll
            for (int mi = 0; mi < 2; mi++) {
                int row = wm + (mi << 4) + r;
                float f0 = Asb[row * SMS + kk + cl];
                float f1 = Asb[(row + 8) * SMS + kk + cl];
                float f2 = Asb[row * SMS + kk + cl + 4];
                float f3 = Asb[(row + 8) * SMS + kk + cl + 4];
                if (phase == 1) {
                    f0 = fmaxf(f0 * scv[kkj][0] + shv[kkj][0], 0.f);
                    f1 = fmaxf(f1 * scv[kkj][0] + shv[kkj][0], 0.f);
                    f2 = fmaxf(f2 * scv[kkj][1] + shv[kkj][1], 0.f);
                    f3 = fmaxf(f3 * scv[kkj][1] + shv[kkj][1], 0.f);
                }
                a[mi][0] = f2tf(f0); a[mi][1] = f2tf(f1);
                a[mi][2] = f2tf(f2); a[mi][3] = f2tf(f3);
            }
            #pragma unroll
            for (int ni = 0; ni < 8; ni++) {
                int nn = wn + (ni << 3) + r;
                b[ni][0] = f2tf(Bsb[nn * SMS + kk + cl]);
                b[ni][1] = f2tf(Bsb[nn * SMS + kk + cl + 4]);
            }
            #pragma unroll
            for (int mi = 0; mi < 2; mi++)
                #pragma unroll
                for (int ni = 0; ni < 8; ni++)
                    mma_tf32(acc[mi][ni], a[mi], b[ni]);
        }
        __syncthreads();
    }

    #pragma unroll
    for (int mi = 0; mi < 2; mi++) {
        int row0 = m0 + wm + (mi << 4) + r;
        #pragma unroll
        for (int ni = 0; ni < 8; ni++) {
            int col = n0 + wn + (ni << 3) + (cl << 1);
            if (row0 < M)
                *(float2*)&C[(size_t)row0 * N + col] = make_float2(acc[mi][ni][0], acc[mi][ni][1]);
            if (row0 + 8 < M)
                *(float2*)&C[(size_t)(row0 + 8) * N + col] = make_float2(acc[mi][ni][2], acc[mi][ni][3]);
        }
    }

    // fused BN-1 column stats (padded rows have A=0 -> acc=0 -> contribute nothing)
    if (phase == 0) {
        if (tid < 128) { s_sum[tid] = 0.f; s_sq[tid] = 0.f; }
        __syncthreads();
        #pragma unroll
        for (int ni = 0; ni < 8; ni++) {
            int c0 = wn + (ni << 3) + (cl << 1);
            float v0 = acc[0][ni][0] + acc[0][ni][2] + acc[1][ni][0] + acc[1][ni][2];
            float q0 = acc[0][ni][0] * acc[0][ni][0] + acc[0][ni][2] * acc[0][ni][2]
                     + acc[1][ni][0] * acc[1][ni][0] + acc[1][ni][2] * acc[1][ni][2];
            float v1 = acc[0][ni][1] + acc[0][ni][3] + acc[1][ni][1] + acc[1][ni][3];
            float q1 = acc[0][ni][1] * acc[0][ni][1] + acc[0][ni][3] * acc[0][ni][3]
                     + acc[1][ni][1] * acc[1][ni][1] + acc[1][ni][3] * acc[1][ni][3];
            atomicAdd(&s_sum[c0], v0);     atomicAdd(&s_sq[c0], q0);
            atomicAdd(&s_sum[c0 + 1], v1); atomicAdd(&s_sq[c0 + 1], q1);
        }
        __syncthreads();
        if (tid < 128) {
            atomicAdd(&g_sumA[n0 + tid], s_sum[tid]);
            atomicAdd(&g_sqA[n0 + tid], s_sq[tid]);
        }
    }
}

// ---------------- batchnorm finalize + final fused epilogue ----------------
__global__ void bn_finalize_kernel(const float* __restrict__ g, const float* __restrict__ b,
                                   int Nrows, int C, int phase) {
    const float* sum = (phase == 0) ? g_sumA : g_sumB;
    const float* sq  = (phase == 0) ? g_sqA  : g_sqB;
    float* scale = (phase == 0) ? g_scaleA : g_scaleB;
    float* shift = (phase == 0) ? g_shiftA : g_shiftB;
    int f = blockIdx.x * blockDim.x + threadIdx.x;
    if (f < C) {
        float invN = 1.f / (float)Nrows;
        float m = sum[f] * invN;
        float v = sq[f] * invN - m * m;
        float sc = g[f] * rsqrtf(v + EPSF);
        scale[f] = sc;
        shift[f] = b[f] - m * sc;
    }
}

// out = relu(out*scaleB + shiftB + x), float4
__global__ void final_kernel(float4* __restrict__ out, const float4* __restrict__ x,
                             int total4, int mask4) {
    int i = blockIdx.x * blockDim.x + threadIdx.x;
    if (i < total4) {
        int f = (i & mask4) << 2;
        float4 sc = *(const float4*)&g_scaleB[f];
        float4 sh = *(const float4*)&g_shiftB[f];
        float4 o = out[i];
        float4 xv = __ldg(&x[i]);
        o.x = fmaxf(o.x * sc.x + sh.x + xv.x, 0.f);
        o.y = fmaxf(o.y * sc.y + sh.y + xv.y, 0.f);
        o.z = fmaxf(o.z * sc.z + sh.z + xv.z, 0.f);
        o.w = fmaxf(o.w * sc.w + sh.w + xv.w, 0.f);
        out[i] = o;
    }
}

// ---------------- launch ----------------
extern "C" void kernel_launch(void* const* d_in, const int* in_sizes, int n_in,
                              void* d_out, int out_size) {
    const float* x  = (const float*)d_in[0];
    const int*   es = (const int*)d_in[1];      // harness materializes int64 as int32
    const float* W1 = (const float*)d_in[2];
    const float* g1 = (const float*)d_in[3];
    const float* b1 = (const float*)d_in[4];
    const float* W2 = (const float*)d_in[5];
    const float* g2 = (const float*)d_in[6];
    const float* b2 = (const float*)d_in[7];
    float* out = (float*)d_out;

    int IC = in_sizes[3];            // 512
    int C  = in_sizes[2] / IC;       // 256
    int N  = in_sizes[0] / C;        // 10000
    int E  = in_sizes[1] / 2;        // 160000

    const int TB = 256;

    static int smem_set = 0;
    if (!smem_set) {
        cudaFuncSetAttribute(gemm_mma, cudaFuncAttributeMaxDynamicSharedMemorySize, GEMM_SMEM);
        smem_set = 1;
    }

    init_kernel<<<(N + TB - 1) / TB, TB>>>(N);
    fill_kernel<<<(E / 2 + TB - 1) / TB, TB>>>(es, E, N);
    dis_kernel<<<(N + TB - 1) / TB, TB>>>(N);

    // conv1: (A_hat x) W1^T  (stats fused into GEMM epilogue)
    aggregate_kernel<<<625, 256>>>((const float4*)x, nullptr, 0, N);
    {
        dim3 grid((IC + 127) / 128, (N + 127) / 128);
        gemm_mma<<<grid, 256, GEMM_SMEM>>>(W1, N, IC, C, 0);
    }
    bn_finalize_kernel<<<1, IC>>>(g1, b1, N, IC, 0);

    // conv2: A_hat (relu(bn(t1)) W2^T)  (BN+ReLU fused into GEMM fragment load,
    //        BN-2 stats fused into aggregation)
    {
        dim3 grid((C + 127) / 128, (N + 127) / 128);
        gemm_mma<<<grid, 256, GEMM_SMEM>>>(W2, N, C, IC, 1);
    }
    aggregate_kernel<<<625, 256>>>(nullptr, (float4*)out, 1, N);
    bn_finalize_kernel<<<1, C>>>(g2, b2, N, C, 1);
    final_kernel<<<(N * C / 4 + TB - 1) / TB, TB>>>((float4*)out, (const float4*)x,
                                                    N * C / 4, C / 4 - 1);
}

// round 11
// speedup vs baseline: 1.0451x; 1.0451x over previous
#include <cuda_runtime.h>

#define EPSF 1e-5f
#define NN 10000
#define EE 160000
#define C1 256
#define C2 512
#define CAP 96   // max neighbors per node; in-degree ~ Poisson(16), max over 10k nodes ~ 45

// ---------------- scratch (static __device__ globals; addresses never taken on host) ----
__device__ float g_dis[NN];
__device__ int   g_cursor[NN];
__device__ int   g_csr[(size_t)NN * CAP];
__device__ __align__(16) float g_agg1[(size_t)NN * C1];
__device__ __align__(16) float g_t1[(size_t)NN * C2];
__device__ __align__(16) float g_y[(size_t)NN * C1];
__device__ __align__(16) float g_sumA[C2], g_sqA[C2], g_scaleA[C2], g_shiftA[C2];
__device__ __align__(16) float g_sumB[C1], g_sqB[C1], g_scaleB[C1], g_shiftB[C1];

// ---------------- graph preprocessing ----------------
__global__ void init_kernel(int n) {
    int i = blockIdx.x * blockDim.x + threadIdx.x;
    if (i < n) g_cursor[i] = 0;
    if (i < C2) { g_sumA[i] = 0.f; g_sqA[i] = 0.f; }
    if (i < C1) { g_sumB[i] = 0.f; g_sqB[i] = 0.f; }
}

// direct bucket scatter, 2 edges per thread
__global__ void fill_kernel(const int* __restrict__ es, int E, int n) {
    int e2 = (blockIdx.x * blockDim.x + threadIdx.x) * 2;
    if (e2 + 1 < E) {
        int2 rr = *(const int2*)&es[e2];
        int2 cc = *(const int2*)&es[E + e2];
        if ((unsigned)rr.x < (unsigned)n && (unsigned)cc.x < (unsigned)n) {
            int pos = atomicAdd(&g_cursor[cc.x], 1);
            if (pos < CAP) g_csr[(size_t)cc.x * CAP + pos] = rr.x;
        }
        if ((unsigned)rr.y < (unsigned)n && (unsigned)cc.y < (unsigned)n) {
            int pos = atomicAdd(&g_cursor[cc.y], 1);
            if (pos < CAP) g_csr[(size_t)cc.y * CAP + pos] = rr.y;
        }
    }
}

__global__ void dis_kernel(int n) {
    int i = blockIdx.x * blockDim.x + threadIdx.x;
    if (i < n) g_dis[i] = rsqrtf((float)(g_cursor[i] + 1));   // +1 self loop
}

// ---------------- normalized aggregation: out = D^-1/2 (A+I) D^-1/2 * in ----------------
// C = 256 -> 64 float4 lanes/node, 4 nodes per 256-thread block, 2500 blocks (1 node/group).
// Simple dependent-load loop (ptxas pipelines it); occupancy does the latency hiding.
// phase 1 additionally accumulates BN-2 stats.
__global__ void __launch_bounds__(256) aggregate_kernel(const float4* __restrict__ xin,
                                                        float4* __restrict__ xout,
                                                        int phase, int nNodes) {
    const float4* in  = (phase == 0) ? xin : (const float4*)g_y;
    float4*       out = (phase == 0) ? (float4*)g_agg1 : xout;
    __shared__ float s_sum[4][C1];
    __shared__ float s_sq[4][C1];
    int sub = threadIdx.x >> 6;
    int l = threadIdx.x & 63;
    int node = blockIdx.x * 4 + sub;

    float4 acc = make_float4(0.f, 0.f, 0.f, 0.f);
    if (node < nNodes) {
        float dc = g_dis[node];
        float w0 = dc * dc;
        float4 v = __ldg(&in[(size_t)node * 64 + l]);
        acc = make_float4(v.x * w0, v.y * w0, v.z * w0, v.w * w0);
        int base = node * CAP;
        int cnt = g_cursor[node];
        if (cnt > CAP) cnt = CAP;
        for (int i = 0; i < cnt; i++) {
            int r = __ldg(&g_csr[base + i]);
            float w = __ldg(&g_dis[r]) * dc;
            float4 u = __ldg(&in[(size_t)r * 64 + l]);
            acc.x += u.x * w; acc.y += u.y * w; acc.z += u.z * w; acc.w += u.w * w;
        }
        out[(size_t)node * 64 + l] = acc;
    }

    if (phase == 1) {
        int f = l << 2;
        s_sum[sub][f] = acc.x; s_sum[sub][f + 1] = acc.y;
        s_sum[sub][f + 2] = acc.z; s_sum[sub][f + 3] = acc.w;
        s_sq[sub][f] = acc.x * acc.x; s_sq[sub][f + 1] = acc.y * acc.y;
        s_sq[sub][f + 2] = acc.z * acc.z; s_sq[sub][f + 3] = acc.w * acc.w;
        __syncthreads();
        if (threadIdx.x < C1) {
            int t = threadIdx.x;
            float ts = s_sum[0][t] + s_sum[1][t] + s_sum[2][t] + s_sum[3][t];
            float tq = s_sq[0][t] + s_sq[1][t] + s_sq[2][t] + s_sq[3][t];
            atomicAdd(&g_sumB[t], ts);
            atomicAdd(&g_sqB[t], tq);
        }
    }
}

// ---------------- tf32 mma.sync GEMM with cp.async double buffering ----------------
// C[M,N] = A[M,K] * B[N,K]^T
// phase 0: A = g_agg1 [M,256], C = g_t1 [M,512]; epilogue accumulates BN-1 column stats
// phase 1: A = relu(g_t1*scaleA+shiftA) [M,512] (BN fused per-fragment), C = g_y [M,256]
// BM=BN=128, BK=32, 256 threads (8 warps, 4x2), warp tile 32x64, m16n8k8 tf32.

__device__ __forceinline__ unsigned f2tf(float f) {
    unsigned u;
    asm("cvt.rna.tf32.f32 %0, %1;" : "=r"(u) : "f"(f));
    return u;
}

__device__ __forceinline__ void mma_tf32(float* c, const unsigned* a, const unsigned* b) {
    asm volatile(
        "mma.sync.aligned.m16n8k8.row.col.f32.tf32.tf32.f32 "
        "{%0,%1,%2,%3}, {%4,%5,%6,%7}, {%8,%9}, {%0,%1,%2,%3};"
        : "+f"(c[0]), "+f"(c[1]), "+f"(c[2]), "+f"(c[3])
        : "r"(a[0]), "r"(a[1]), "r"(a[2]), "r"(a[3]), "r"(b[0]), "r"(b[1]));
}

__device__ __forceinline__ void cp16(void* smem_dst, const void* gmem_src, bool valid) {
    unsigned dst = (unsigned)__cvta_generic_to_shared(smem_dst);
    int sz = valid ? 16 : 0;
    asm volatile("cp.async.cg.shared.global [%0], [%1], 16, %2;"
                 :: "r"(dst), "l"(gmem_src), "r"(sz));
}

#define SMS 36                    // smem row stride (floats): bank = (4r + c) % 32, conflict-free
#define TILE_F (128 * SMS)        // floats per stage per matrix
#define GEMM_SMEM (4 * TILE_F * 4)  // 2 stages x 2 matrices, bytes = 73728

__global__ void __launch_bounds__(256) gemm_mma(const float* __restrict__ B,
                                                int M, int N, int K, int phase) {
    const float* A = (phase == 0) ? (const float*)g_agg1 : (const float*)g_t1;
    float*       C = (phase == 0) ? (float*)g_t1 : (float*)g_y;

    extern __shared__ float smem[];
    float* As = smem;                 // [2][128][SMS]
    float* Bs = smem + 2 * TILE_F;    // [2][128][SMS]
    __shared__ float s_sum[128];
    __shared__ float s_sq[128];

    int tid = threadIdx.x;
    int lane = tid & 31, wid = tid >> 5;
    int wm = (wid & 3) << 5;     // 0,32,64,96
    int wn = (wid >> 2) << 6;    // 0,64
    int m0 = blockIdx.y << 7, n0 = blockIdx.x << 7;

    float acc[2][8][4];
    #pragma unroll
    for (int mi = 0; mi < 2; mi++)
        #pragma unroll
        for (int ni = 0; ni < 8; ni++)
            #pragma unroll
            for (int j = 0; j < 4; j++) acc[mi][ni][j] = 0.f;

    int r = lane >> 2, cl = lane & 3;
    int ldr = tid >> 3;            // 0..31: row group base for loads
    int ldc = (tid & 7) << 2;      // 0,4,...,28

    int kTiles = K >> 5;

    // prologue: stage 0 <- tile 0
    {
        #pragma unroll
        for (int i = 0; i < 4; i++) {
            int row = ldr + (i << 5);
            cp16(&As[row * SMS + ldc], &A[(size_t)(m0 + row) * K + ldc], m0 + row < M);
            cp16(&Bs[row * SMS + ldc], &B[(size_t)(n0 + row) * K + ldc], true);
        }
        asm volatile("cp.async.commit_group;");
    }

    for (int t = 0; t < kTiles; t++) {
        int s = t & 1;
        if (t + 1 < kTiles) {
            int sn = (t + 1) & 1;
            int kofs = (t + 1) << 5;
            #pragma unroll
            for (int i = 0; i < 4; i++) {
                int row = ldr + (i << 5);
                cp16(&As[sn * TILE_F + row * SMS + ldc],
                     &A[(size_t)(m0 + row) * K + kofs + ldc], m0 + row < M);
                cp16(&Bs[sn * TILE_F + row * SMS + ldc],
                     &B[(size_t)(n0 + row) * K + kofs + ldc], true);
            }
            asm volatile("cp.async.commit_group;");
            asm volatile("cp.async.wait_group 1;");
        } else {
            asm volatile("cp.async.wait_group 0;");
        }
        __syncthreads();

        // preload BN params for this k-tile (phase 1)
        float scv[4][2], shv[4][2];
        if (phase == 1) {
            int kb = t << 5;
            #pragma unroll
            for (int kkj = 0; kkj < 4; kkj++) {
                scv[kkj][0] = __ldg(&g_scaleA[kb + (kkj << 3) + cl]);
                scv[kkj][1] = __ldg(&g_scaleA[kb + (kkj << 3) + cl + 4]);
                shv[kkj][0] = __ldg(&g_shiftA[kb + (kkj << 3) + cl]);
                shv[kkj][1] = __ldg(&g_shiftA[kb + (kkj << 3) + cl + 4]);
            }
        }

        const float* Asb = As + s * TILE_F;
        const float* Bsb = Bs + s * TILE_F;

        #pragma unroll
        for (int kkj = 0; kkj < 4; kkj++) {
            int kk = kkj << 3;
            unsigned a[2][4], b[8][2];
            #pragma unroll
            for (int mi = 0; mi < 2; mi++) {
                int row = wm + (mi << 4) + r;
                float f0 = Asb[row * SMS + kk + cl];
                float f1 = Asb[(row + 8) * SMS + kk + cl];
                float f2 = Asb[row * SMS + kk + cl + 4];
                float f3 = Asb[(row + 8) * SMS + kk + cl + 4];
                if (phase == 1) {
                    f0 = fmaxf(f0 * scv[kkj][0] + shv[kkj][0], 0.f);
                    f1 = fmaxf(f1 * scv[kkj][0] + shv[kkj][0], 0.f);
                    f2 = fmaxf(f2 * scv[kkj][1] + shv[kkj][1], 0.f);
                    f3 = fmaxf(f3 * scv[kkj][1] + shv[kkj][1], 0.f);
                }
                a[mi][0] = f2tf(f0); a[mi][1] = f2tf(f1);
                a[mi][2] = f2tf(f2); a[mi][3] = f2tf(f3);
            }
            #pragma unroll
            for (int ni = 0; ni < 8; ni++) {
                int nn = wn + (ni << 3) + r;
                b[ni][0] = f2tf(Bsb[nn * SMS + kk + cl]);
                b[ni][1] = f2tf(Bsb[nn * SMS + kk + cl + 4]);
            }
            #pragma unroll
            for (int mi = 0; mi < 2; mi++)
                #pragma unroll
                for (int ni = 0; ni < 8; ni++)
                    mma_tf32(acc[mi][ni], a[mi], b[ni]);
        }
        __syncthreads();
    }

    #pragma unroll
    for (int mi = 0; mi < 2; mi++) {
        int row0 = m0 + wm + (mi << 4) + r;
        #pragma unroll
        for (int ni = 0; ni < 8; ni++) {
            int col = n0 + wn + (ni << 3) + (cl << 1);
            if (row0 < M)
                *(float2*)&C[(size_t)row0 * N + col] = make_float2(acc[mi][ni][0], acc[mi][ni][1]);
            if (row0 + 8 < M)
                *(float2*)&C[(size_t)(row0 + 8) * N + col] = make_float2(acc[mi][ni][2], acc[mi][ni][3]);
        }
    }

    // fused BN-1 column stats (padded rows have A=0 -> acc=0 -> contribute nothing)
    if (phase == 0) {
        if (tid < 128) { s_sum[tid] = 0.f; s_sq[tid] = 0.f; }
        __syncthreads();
        #pragma unroll
        for (int ni = 0; ni < 8; ni++) {
            int c0 = wn + (ni << 3) + (cl << 1);
            float v0 = acc[0][ni][0] + acc[0][ni][2] + acc[1][ni][0] + acc[1][ni][2];
            float q0 = acc[0][ni][0] * acc[0][ni][0] + acc[0][ni][2] * acc[0][ni][2]
                     + acc[1][ni][0] * acc[1][ni][0] + acc[1][ni][2] * acc[1][ni][2];
            float v1 = acc[0][ni][1] + acc[0][ni][3] + acc[1][ni][1] + acc[1][ni][3];
            float q1 = acc[0][ni][1] * acc[0][ni][1] + acc[0][ni][3] * acc[0][ni][3]
                     + acc[1][ni][1] * acc[1][ni][1] + acc[1][ni][3] * acc[1][ni][3];
            atomicAdd(&s_sum[c0], v0);     atomicAdd(&s_sq[c0], q0);
            atomicAdd(&s_sum[c0 + 1], v1); atomicAdd(&s_sq[c0 + 1], q1);
        }
        __syncthreads();
        if (tid < 128) {
            atomicAdd(&g_sumA[n0 + tid], s_sum[tid]);
            atomicAdd(&g_sqA[n0 + tid], s_sq[tid]);
        }
    }
}

// ---------------- batchnorm finalize + final fused epilogue ----------------
__global__ void bn_finalize_kernel(const float* __restrict__ g, const float* __restrict__ b,
                                   int Nrows, int C, int phase) {
    const float* sum = (phase == 0) ? g_sumA : g_sumB;
    const float* sq  = (phase == 0) ? g_sqA  : g_sqB;
    float* scale = (phase == 0) ? g_scaleA : g_scaleB;
    float* shift = (phase == 0) ? g_shiftA : g_shiftB;
    int f = blockIdx.x * blockDim.x + threadIdx.x;
    if (f < C) {
        float invN = 1.f / (float)Nrows;
        float m = sum[f] * invN;
        float v = sq[f] * invN - m * m;
        float sc = g[f] * rsqrtf(v + EPSF);
        scale[f] = sc;
        shift[f] = b[f] - m * sc;
    }
}

// out = relu(out*scaleB + shiftB + x), float4
__global__ void final_kernel(float4* __restrict__ out, const float4* __restrict__ x,
                             int total4, int mask4) {
    int i = blockIdx.x * blockDim.x + threadIdx.x;
    if (i < total4) {
        int f = (i & mask4) << 2;
        float4 sc = *(const float4*)&g_scaleB[f];
        float4 sh = *(const float4*)&g_shiftB[f];
        float4 o = out[i];
        float4 xv = __ldg(&x[i]);
        o.x = fmaxf(o.x * sc.x + sh.x + xv.x, 0.f);
        o.y = fmaxf(o.y * sc.y + sh.y + xv.y, 0.f);
        o.z = fmaxf(o.z * sc.z + sh.z + xv.z, 0.f);
        o.w = fmaxf(o.w * sc.w + sh.w + xv.w, 0.f);
        out[i] = o;
    }
}

// ---------------- launch ----------------
extern "C" void kernel_launch(void* const* d_in, const int* in_sizes, int n_in,
                              void* d_out, int out_size) {
    const float* x  = (const float*)d_in[0];
    const int*   es = (const int*)d_in[1];      // harness materializes int64 as int32
    const float* W1 = (const float*)d_in[2];
    const float* g1 = (const float*)d_in[3];
    const float* b1 = (const float*)d_in[4];
    const float* W2 = (const float*)d_in[5];
    const float* g2 = (const float*)d_in[6];
    const float* b2 = (const float*)d_in[7];
    float* out = (float*)d_out;

    int IC = in_sizes[3];            // 512
    int C  = in_sizes[2] / IC;       // 256
    int N  = in_sizes[0] / C;        // 10000
    int E  = in_sizes[1] / 2;        // 160000

    const int TB = 256;

    static int smem_set = 0;
    if (!smem_set) {
        cudaFuncSetAttribute(gemm_mma, cudaFuncAttributeMaxDynamicSharedMemorySize, GEMM_SMEM);
        smem_set = 1;
    }

    init_kernel<<<(N + TB - 1) / TB, TB>>>(N);
    fill_kernel<<<(E / 2 + TB - 1) / TB, TB>>>(es, E, N);
    dis_kernel<<<(N + TB - 1) / TB, TB>>>(N);

    // conv1: (A_hat x) W1^T  (stats fused into GEMM epilogue)
    aggregate_kernel<<<(N + 3) / 4, 256>>>((const float4*)x, nullptr, 0, N);
    {
        dim3 grid((IC + 127) / 128, (N + 127) / 128);
        gemm_mma<<<grid, 256, GEMM_SMEM>>>(W1, N, IC, C, 0);
    }
    bn_finalize_kernel<<<1, IC>>>(g1, b1, N, IC, 0);

    // conv2: A_hat (relu(bn(t1)) W2^T)  (BN+ReLU fused into GEMM fragment load,
    //        BN-2 stats fused into aggregation)
    {
        dim3 grid((C + 127) / 128, (N + 127) / 128);
        gemm_mma<<<grid, 256, GEMM_SMEM>>>(W2, N, C, IC, 1);
    }
    aggregate_kernel<<<(N + 3) / 4, 256>>>(nullptr, (float4*)out, 1, N);
    bn_finalize_kernel<<<1, C>>>(g2, b2, N, C, 1);
    final_kernel<<<(N * C / 4 + TB - 1) / TB, TB>>>((float4*)out, (const float4*)x,
                                                    N * C / 4, C / 4 - 1);
}

// round 14
// speedup vs baseline: 1.3597x; 1.3011x over previous
#include <cuda_runtime.h>
#include <cuda_fp16.h>
#include <cstdint>

#define EPSF 1e-5f
#define NN 10000
#define EE 160000
#define C1 256
#define C2 512
#define CAP 96   // max neighbors per node; in-degree ~ Poisson(16), max over 10k nodes ~ 45

// ---------------- scratch (static __device__ globals; addresses never taken on host) ----
__device__ float g_dis[NN];
__device__ int   g_cursor[NN];
__device__ int   g_csr[(size_t)NN * CAP];
__device__ __align__(16) float g_agg1[(size_t)NN * C1];
__device__ __align__(16) float g_t1[(size_t)NN * C2];
__device__ __align__(16) float g_y[(size_t)NN * C1];
__device__ __align__(16) float g_sumA[C2], g_sqA[C2], g_scaleA[C2], g_shiftA[C2];
__device__ __align__(16) float g_sumB[C1], g_sqB[C1];

// ---------------- graph preprocessing ----------------
__global__ void init_kernel(int n) {
    int i = blockIdx.x * blockDim.x + threadIdx.x;
    if (i < n) g_cursor[i] = 0;
    if (i < C2) { g_sumA[i] = 0.f; g_sqA[i] = 0.f; }
    if (i < C1) { g_sumB[i] = 0.f; g_sqB[i] = 0.f; }
}

__global__ void fill_kernel(const int* __restrict__ es, int E, int n) {
    int e2 = (blockIdx.x * blockDim.x + threadIdx.x) * 2;
    if (e2 + 1 < E) {
        int2 rr = *(const int2*)&es[e2];
        int2 cc = *(const int2*)&es[E + e2];
        if ((unsigned)rr.x < (unsigned)n && (unsigned)cc.x < (unsigned)n) {
            int pos = atomicAdd(&g_cursor[cc.x], 1);
            if (pos < CAP) g_csr[(size_t)cc.x * CAP + pos] = rr.x;
        }
        if ((unsigned)rr.y < (unsigned)n && (unsigned)cc.y < (unsigned)n) {
            int pos = atomicAdd(&g_cursor[cc.y], 1);
            if (pos < CAP) g_csr[(size_t)cc.y * CAP + pos] = rr.y;
        }
    }
}

__global__ void dis_kernel(int n) {
    int i = blockIdx.x * blockDim.x + threadIdx.x;
    if (i < n) g_dis[i] = rsqrtf((float)(g_cursor[i] + 1));   // +1 self loop
}

// ---------------- normalized aggregation: out = D^-1/2 (A+I) D^-1/2 * in ----------------
// R9 config: 625 blocks, grid-stride, 4 nodes/block; phase 1 fuses BN-2 stats.
__global__ void __launch_bounds__(256) aggregate_kernel(const float4* __restrict__ xin,
                                                        float4* __restrict__ xout,
                                                        int phase, int nNodes) {
    const float4* in  = (phase == 0) ? xin : (const float4*)g_y;
    float4*       out = (phase == 0) ? (float4*)g_agg1 : xout;
    __shared__ float s_sum[4][C1];
    __shared__ float s_sq[4][C1];
    int sub = threadIdx.x >> 6;
    int l = threadIdx.x & 63;
    float4 ls = make_float4(0.f, 0.f, 0.f, 0.f);
    float4 lq = make_float4(0.f, 0.f, 0.f, 0.f);

    for (int node = blockIdx.x * 4 + sub; node < nNodes; node += gridDim.x * 4) {
        float dc = g_dis[node];
        float w0 = dc * dc;
        float4 v = __ldg(&in[(size_t)node * 64 + l]);
        float4 acc = make_float4(v.x * w0, v.y * w0, v.z * w0, v.w * w0);
        int base = node * CAP;
        int cnt = g_cursor[node];
        if (cnt > CAP) cnt = CAP;
        for (int i = 0; i < cnt; i++) {
            int r = __ldg(&g_csr[base + i]);
            float w = __ldg(&g_dis[r]) * dc;
            float4 u = __ldg(&in[(size_t)r * 64 + l]);
            acc.x += u.x * w; acc.y += u.y * w; acc.z += u.z * w; acc.w += u.w * w;
        }
        out[(size_t)node * 64 + l] = acc;
        if (phase == 1) {
            ls.x += acc.x; ls.y += acc.y; ls.z += acc.z; ls.w += acc.w;
            lq.x += acc.x * acc.x; lq.y += acc.y * acc.y;
            lq.z += acc.z * acc.z; lq.w += acc.w * acc.w;
        }
    }

    if (phase == 1) {
        int f = l << 2;
        s_sum[sub][f] = ls.x; s_sum[sub][f + 1] = ls.y;
        s_sum[sub][f + 2] = ls.z; s_sum[sub][f + 3] = ls.w;
        s_sq[sub][f] = lq.x; s_sq[sub][f + 1] = lq.y;
        s_sq[sub][f + 2] = lq.z; s_sq[sub][f + 3] = lq.w;
        __syncthreads();
        if (threadIdx.x < C1) {
            int t = threadIdx.x;
            atomicAdd(&g_sumB[t], s_sum[0][t] + s_sum[1][t] + s_sum[2][t] + s_sum[3][t]);
            atomicAdd(&g_sqB[t], s_sq[0][t] + s_sq[1][t] + s_sq[2][t] + s_sq[3][t]);
        }
    }
}

// ---------------- fp16 mma.sync GEMM: C[M,N] = A[M,K] * B[N,K]^T ----------------
// phase 0: A = g_agg1 [M,256], C = g_t1 [M,512]; epilogue accumulates BN-1 column stats
// phase 1: A = relu(g_t1*scaleA+shiftA) [M,512] (BN fused in half-convert), C = g_y [M,256]
// BM=BN=128, BK=32, 256 threads (8 warps, 4x2), warp tile 32x64, m16n8k16 f16.f32.
// smem: halves, row stride 40 halves = 20 words -> all 32 lanes on distinct banks.

__device__ __forceinline__ void mma_f16(float* c, const unsigned* a, const unsigned* b) {
    asm volatile(
        "mma.sync.aligned.m16n8k16.row.col.f32.f16.f16.f32 "
        "{%0,%1,%2,%3}, {%4,%5,%6,%7}, {%8,%9}, {%0,%1,%2,%3};"
        : "+f"(c[0]), "+f"(c[1]), "+f"(c[2]), "+f"(c[3])
        : "r"(a[0]), "r"(a[1]), "r"(a[2]), "r"(a[3]), "r"(b[0]), "r"(b[1]));
}

__device__ __forceinline__ unsigned pack_h2(float lo, float hi) {
    __half2 h = __floats2half2_rn(lo, hi);
    return *(unsigned*)&h;
}

#define SMW 20   // smem row stride in 32-bit words (= 40 halves)

__global__ void __launch_bounds__(256) gemm_h(const float* __restrict__ B,
                                              int M, int N, int K, int phase) {
    const float* A = (phase == 0) ? (const float*)g_agg1 : (const float*)g_t1;
    float*       C = (phase == 0) ? (float*)g_t1 : (float*)g_y;

    __shared__ unsigned As[128][SMW];
    __shared__ unsigned Bs[128][SMW];
    __shared__ float s_sum[128];
    __shared__ float s_sq[128];

    int tid = threadIdx.x;
    int lane = tid & 31, wid = tid >> 5;
    int wm = (wid & 3) << 5;     // 0,32,64,96
    int wn = (wid >> 2) << 6;    // 0,64
    int m0 = blockIdx.y << 7, n0 = blockIdx.x << 7;

    float acc[2][8][4];
    #pragma unroll
    for (int mi = 0; mi < 2; mi++)
        #pragma unroll
        for (int ni = 0; ni < 8; ni++)
            #pragma unroll
            for (int j = 0; j < 4; j++) acc[mi][ni][j] = 0.f;

    int r = lane >> 2, cl = lane & 3;

    for (int k0 = 0; k0 < K; k0 += 32) {
        // load 128x32 of A and B as fp16 (BN+ReLU fused for phase-1 A)
        #pragma unroll
        for (int i = 0; i < 4; i++) {
            int id = tid + (i << 8);          // 0..1023
            int row = id >> 3;                // 0..127
            int c4 = (id & 7) << 2;           // 0,4,...,28
            float4 va = make_float4(0.f, 0.f, 0.f, 0.f);
            if (m0 + row < M) va = *(const float4*)&A[(size_t)(m0 + row) * K + k0 + c4];
            if (phase == 1) {
                float4 sc = *(const float4*)&g_scaleA[k0 + c4];
                float4 sh = *(const float4*)&g_shiftA[k0 + c4];
                va.x = fmaxf(va.x * sc.x + sh.x, 0.f);
                va.y = fmaxf(va.y * sc.y + sh.y, 0.f);
                va.z = fmaxf(va.z * sc.z + sh.z, 0.f);
                va.w = fmaxf(va.w * sc.w + sh.w, 0.f);
            }
            As[row][(c4 >> 1)] = pack_h2(va.x, va.y);
            As[row][(c4 >> 1) + 1] = pack_h2(va.z, va.w);
            float4 vb = *(const float4*)&B[(size_t)(n0 + row) * K + k0 + c4];
            Bs[row][(c4 >> 1)] = pack_h2(vb.x, vb.y);
            Bs[row][(c4 >> 1) + 1] = pack_h2(vb.z, vb.w);
        }
        __syncthreads();

        #pragma unroll
        for (int ks = 0; ks < 2; ks++) {      // two K=16 steps per 32-tile
            int kw = ks << 3;                 // word offset 0 or 8
            unsigned a[2][4], b[8][2];
            #pragma unroll
            for (int mi = 0; mi < 2; mi++) {
                int row = wm + (mi << 4) + r;
                a[mi][0] = As[row][kw + cl];
                a[mi][1] = As[row + 8][kw + cl];
                a[mi][2] = As[row][kw + cl + 4];
                a[mi][3] = As[row + 8][kw + cl + 4];
            }
            #pragma unroll
            for (int ni = 0; ni < 8; ni++) {
                int nn = wn + (ni << 3) + r;
                b[ni][0] = Bs[nn][kw + cl];
                b[ni][1] = Bs[nn][kw + cl + 4];
            }
            #pragma unroll
            for (int mi = 0; mi < 2; mi++)
                #pragma unroll
                for (int ni = 0; ni < 8; ni++)
                    mma_f16(acc[mi][ni], a[mi], b[ni]);
        }
        __syncthreads();
    }

    #pragma unroll
    for (int mi = 0; mi < 2; mi++) {
        int row0 = m0 + wm + (mi << 4) + r;
        #pragma unroll
        for (int ni = 0; ni < 8; ni++) {
            int col = n0 + wn + (ni << 3) + (cl << 1);
            if (row0 < M)
                *(float2*)&C[(size_t)row0 * N + col] = make_float2(acc[mi][ni][0], acc[mi][ni][1]);
            if (row0 + 8 < M)
                *(float2*)&C[(size_t)(row0 + 8) * N + col] = make_float2(acc[mi][ni][2], acc[mi][ni][3]);
        }
    }

    // fused BN-1 column stats (padded rows have A=0 -> acc=0 -> contribute nothing)
    if (phase == 0) {
        if (tid < 128) { s_sum[tid] = 0.f; s_sq[tid] = 0.f; }
        __syncthreads();
        #pragma unroll
        for (int ni = 0; ni < 8; ni++) {
            int c0 = wn + (ni << 3) + (cl << 1);
            float v0 = acc[0][ni][0] + acc[0][ni][2] + acc[1][ni][0] + acc[1][ni][2];
            float q0 = acc[0][ni][0] * acc[0][ni][0] + acc[0][ni][2] * acc[0][ni][2]
                     + acc[1][ni][0] * acc[1][ni][0] + acc[1][ni][2] * acc[1][ni][2];
            float v1 = acc[0][ni][1] + acc[0][ni][3] + acc[1][ni][1] + acc[1][ni][3];
            float q1 = acc[0][ni][1] * acc[0][ni][1] + acc[0][ni][3] * acc[0][ni][3]
                     + acc[1][ni][1] * acc[1][ni][1] + acc[1][ni][3] * acc[1][ni][3];
            atomicAdd(&s_sum[c0], v0);     atomicAdd(&s_sq[c0], q0);
            atomicAdd(&s_sum[c0 + 1], v1); atomicAdd(&s_sq[c0 + 1], q1);
        }
        __syncthreads();
        if (tid < 128) {
            atomicAdd(&g_sumA[n0 + tid], s_sum[tid]);
            atomicAdd(&g_sqA[n0 + tid], s_sq[tid]);
        }
    }
}

// ---------------- batchnorm finalize + final fused epilogue ----------------
__global__ void bn_finalize_kernel(const float* __restrict__ g, const float* __restrict__ b,
                                   int Nrows, int C) {
    int f = blockIdx.x * blockDim.x + threadIdx.x;
    if (f < C) {
        float invN = 1.f / (float)Nrows;
        float m = g_sumA[f] * invN;
        float v = g_sqA[f] * invN - m * m;
        float sc = g[f] * rsqrtf(v + EPSF);
        g_scaleA[f] = sc;
        g_shiftA[f] = b[f] - m * sc;
    }
}

// out = relu(out*scaleB + shiftB + x); BN-2 finalize fused in-kernel
__global__ void __launch_bounds__(256) final_kernel(float4* __restrict__ out,
                                                    const float4* __restrict__ x,
                                                    const float* __restrict__ g,
                                                    const float* __restrict__ b,
                                                    int Nrows, int total4) {
    __shared__ float sc[C1], sh[C1];
    float invN = 1.f / (float)Nrows;
    if (threadIdx.x < C1) {
        int j = threadIdx.x;
        float m = g_sumB[j] * invN;
        float v = g_sqB[j] * invN - m * m;
        float s = g[j] * rsqrtf(v + EPSF);
        sc[j] = s;
        sh[j] = b[j] - m * s;
    }
    __syncthreads();
    int i = blockIdx.x * 256 + threadIdx.x;
    if (i < total4) {
        int f = (i & (C1 / 4 - 1)) << 2;
        float4 o = out[i];
        float4 xv = __ldg(&x[i]);
        o.x = fmaxf(o.x * sc[f] + sh[f] + xv.x, 0.f);
        o.y = fmaxf(o.y * sc[f + 1] + sh[f + 1] + xv.y, 0.f);
        o.z = fmaxf(o.z * sc[f + 2] + sh[f + 2] + xv.z, 0.f);
        o.w = fmaxf(o.w * sc[f + 3] + sh[f + 3] + xv.w, 0.f);
        out[i] = o;
    }
}

// ---------------- launch ----------------
extern "C" void kernel_launch(void* const* d_in, const int* in_sizes, int n_in,
                              void* d_out, int out_size) {
    const float* x  = (const float*)d_in[0];
    const int*   es = (const int*)d_in[1];      // harness materializes int64 as int32
    const float* W1 = (const float*)d_in[2];
    const float* g1 = (const float*)d_in[3];
    const float* b1 = (const float*)d_in[4];
    const float* W2 = (const float*)d_in[5];
    const float* g2 = (const float*)d_in[6];
    const float* b2 = (const float*)d_in[7];
    float* out = (float*)d_out;

    int IC = in_sizes[3];            // 512
    int C  = in_sizes[2] / IC;       // 256
    int N  = in_sizes[0] / C;        // 10000
    int E  = in_sizes[1] / 2;        // 160000

    const int TB = 256;

    init_kernel<<<(N + TB - 1) / TB, TB>>>(N);
    fill_kernel<<<(E / 2 + TB - 1) / TB, TB>>>(es, E, N);
    dis_kernel<<<(N + TB - 1) / TB, TB>>>(N);

    // conv1: (A_hat x) W1^T  (BN-1 stats fused into GEMM epilogue)
    aggregate_kernel<<<625, 256>>>((const float4*)x, nullptr, 0, N);
    {
        dim3 grid(IC / 128, (N + 127) / 128);
        gemm_h<<<grid, 256>>>(W1, N, IC, C, 0);
    }
    bn_finalize_kernel<<<2, 256>>>(g1, b1, N, IC);

    // conv2: A_hat (relu(bn(t1)) W2^T)  (BN+ReLU fused into half-convert,
    //        BN-2 stats fused into aggregation)
    {
        dim3 grid(C / 128, (N + 127) / 128);
        gemm_h<<<grid, 256>>>(W2, N, C, IC, 1);
    }
    aggregate_kernel<<<625, 256>>>(nullptr, (float4*)out, 1, N);
    final_kernel<<<(N * C / 4 + TB - 1) / TB, TB>>>((float4*)out, (const float4*)x,
                                                    g2, b2, N, N * C / 4);
}